// round 11
// baseline (speedup 1.0000x reference)
#include <cuda_runtime.h>
#include <cuda_fp16.h>

// Trilinear interpolation, fp16 cell-table + pipelined cp.async gathers:
//   Pass 1 (repack): y (8,64^3 f32) -> g_tab (8, 63,63, 64-pad cells x 8 fp16
//           corners, 16 B/cell; z padded to 64 so rows are 1024 B = 8 full
//           128B lines -> branch-free, line-aligned stores).
//   Pass 2 (interp): 8 points/thread, gathers via cp.async.cg 16B into smem
//           in TWO commit groups, processed pipelined (wait_group 1 / 0).
//           cp.async has no destination registers -> ptxas cannot collapse
//           the batch (R6/R8 lesson). MLP=8 per thread.

#define VOL     262144       // 64^3
#define MTOT    884736       // 96^3
#define PTS_T   110592       // MTOT/8: threads per batch in interp
#define NC1     63
#define NCPAD   64           // padded z cells per row
#define NC3P    (63 * 63 * 64)   // 254,016 cells per batch (padded)
#define NCELLSP (8 * NC3P)       // 2,032,128

// 32.5 MB static scratch table: one uint4 (8 x fp16) per cell
__device__ uint4 g_tab[NCELLSP];

__device__ __forceinline__ unsigned pack2(float a, float b) {
    __half2 h = __floats2half2_rn(a, b);
    return *reinterpret_cast<unsigned*>(&h);
}

// One thread per 4-cell quad; 16 quads per (b,i,j) row, all unconditional.
// Quad 15 (k0=60) produces pad cell 63 from out-of-row data; interp never
// reads i2 > 62, and the scalar read at element 64 stays inside y.
__global__ void __launch_bounds__(256) repack_kernel(const float* __restrict__ y)
{
    int id = blockIdx.x * blockDim.x + threadIdx.x;
    const int TOTAL = 8 * 63 * 63 * 16;      // 508,032
    if (id >= TOTAL) return;

    int kq = id & 15;
    int r  = id >> 4;                         // (b*63+i)*63+j
    int j  = r % 63;
    int ij = r / 63;
    int i  = ij % 63;
    int b  = ij / 63;
    int k0 = kq * 4;

    const float* p0 = y + (size_t)b * VOL + i * 4096 + j * 64 + k0; // (i,  j  )
    const float* p1 = p0 + 64;                                      // (i,  j+1)
    const float* p2 = p0 + 4096;                                    // (i+1,j  )
    const float* p3 = p0 + 4160;                                    // (i+1,j+1)

    float4 q0 = __ldg(reinterpret_cast<const float4*>(p0));
    float4 q1 = __ldg(reinterpret_cast<const float4*>(p1));
    float4 q2 = __ldg(reinterpret_cast<const float4*>(p2));
    float4 q3 = __ldg(reinterpret_cast<const float4*>(p3));
    float e0 = __ldg(p0 + 4);
    float e1 = __ldg(p1 + 4);
    float e2 = __ldg(p2 + 4);
    float e3 = __ldg(p3 + 4);

    float a0[5] = {q0.x, q0.y, q0.z, q0.w, e0};
    float a1[5] = {q1.x, q1.y, q1.z, q1.w, e1};
    float a2[5] = {q2.x, q2.y, q2.z, q2.w, e2};
    float a3[5] = {q3.x, q3.y, q3.z, q3.w, e3};

    size_t cbase = (size_t)((b * 63 + i) * 63 + j) * NCPAD + k0;

#pragma unroll
    for (int c = 0; c < 4; c++) {
        uint4 cell;
        cell.x = pack2(a0[c], a0[c + 1]);   // v000, v001
        cell.y = pack2(a1[c], a1[c + 1]);   // v010, v011
        cell.z = pack2(a2[c], a2[c + 1]);   // v100, v101
        cell.w = pack2(a3[c], a3[c + 1]);   // v110, v111
        g_tab[cbase + c] = cell;
    }
}

__device__ __forceinline__ float lerp1(float a, float b, float t) {
    return fmaf(t, b - a, a);
}

__device__ __forceinline__ float2 h2f(unsigned u) {
    __half2 h = *reinterpret_cast<__half2*>(&u);
    return __half22float2(h);
}

__device__ __forceinline__ unsigned smem_u32(const void* p) {
    return (unsigned)__cvta_generic_to_shared(p);
}

__global__ void __launch_bounds__(256) trilerp_kernel(
    const float* __restrict__ xn,
    float* __restrict__ out)
{
    __shared__ uint4 stage[8 * 256];          // 32 KB: stage[p*256 + tid]

    int tid = threadIdx.x;
    int t = blockIdx.x * 256 + tid;           // grid sized exactly

    // 8 points = 24 floats = 6 float4 (streaming, evict-first)
    const float4* xv = reinterpret_cast<const float4*>(xn) + (size_t)t * 6;
    float4 X[6];
#pragma unroll
    for (int i = 0; i < 6; i++) X[i] = __ldcs(xv + i);
    float c[24] = {X[0].x, X[0].y, X[0].z, X[0].w,
                   X[1].x, X[1].y, X[1].z, X[1].w,
                   X[2].x, X[2].y, X[2].z, X[2].w,
                   X[3].x, X[3].y, X[3].z, X[3].w,
                   X[4].x, X[4].y, X[4].z, X[4].w,
                   X[5].x, X[5].y, X[5].z, X[5].w};

    int base = (t / PTS_T) * NC3P;            // batch table base

    float f0[8], f1[8], f2[8];

    // Group A: points 0..3 — compute + fire gathers
#pragma unroll
    for (int p = 0; p < 4; p++) {
        float r0 = c[3 * p + 0] * 63.0f;
        float r1 = c[3 * p + 1] * 63.0f;
        float r2 = c[3 * p + 2] * 63.0f;
        int i0 = min((int)r0, 62);
        int i1 = min((int)r1, 62);
        int i2 = min((int)r2, 62);
        f0[p] = r0 - (float)i0;
        f1[p] = r1 - (float)i1;
        f2[p] = r2 - (float)i2;
        int cell = base + ((i0 * NC1 + i1) << 6) + i2;
        unsigned saddr = smem_u32(&stage[p * 256 + tid]);
        const uint4* gptr = g_tab + cell;
        asm volatile("cp.async.cg.shared.global [%0], [%1], 16;"
                     :: "r"(saddr), "l"(gptr) : "memory");
    }
    asm volatile("cp.async.commit_group;");

    // Group B: points 4..7
#pragma unroll
    for (int p = 4; p < 8; p++) {
        float r0 = c[3 * p + 0] * 63.0f;
        float r1 = c[3 * p + 1] * 63.0f;
        float r2 = c[3 * p + 2] * 63.0f;
        int i0 = min((int)r0, 62);
        int i1 = min((int)r1, 62);
        int i2 = min((int)r2, 62);
        f0[p] = r0 - (float)i0;
        f1[p] = r1 - (float)i1;
        f2[p] = r2 - (float)i2;
        int cell = base + ((i0 * NC1 + i1) << 6) + i2;
        unsigned saddr = smem_u32(&stage[p * 256 + tid]);
        const uint4* gptr = g_tab + cell;
        asm volatile("cp.async.cg.shared.global [%0], [%1], 16;"
                     :: "r"(saddr), "l"(gptr) : "memory");
    }
    asm volatile("cp.async.commit_group;");

    float4* o = reinterpret_cast<float4*>(out) + (size_t)t * 2;

    // Process group A while group B is still in flight
    asm volatile("cp.async.wait_group 1;" ::: "memory");
    {
        float4 res;
        float* rp = &res.x;
#pragma unroll
        for (int p = 0; p < 4; p++) {
            uint4 q = stage[p * 256 + tid];
            float2 e0 = h2f(q.x);
            float2 e1 = h2f(q.y);
            float2 e2 = h2f(q.z);
            float2 e3 = h2f(q.w);
            float v00 = lerp1(e0.x, e0.y, f2[p]);
            float v01 = lerp1(e1.x, e1.y, f2[p]);
            float v10 = lerp1(e2.x, e2.y, f2[p]);
            float v11 = lerp1(e3.x, e3.y, f2[p]);
            float v0  = lerp1(v00, v01, f1[p]);
            float v1  = lerp1(v10, v11, f1[p]);
            rp[p]     = lerp1(v0, v1, f0[p]);
        }
        __stcs(o, res);
    }

    // Process group B
    asm volatile("cp.async.wait_group 0;" ::: "memory");
    {
        float4 res;
        float* rp = &res.x;
#pragma unroll
        for (int p = 4; p < 8; p++) {
            uint4 q = stage[p * 256 + tid];
            float2 e0 = h2f(q.x);
            float2 e1 = h2f(q.y);
            float2 e2 = h2f(q.z);
            float2 e3 = h2f(q.w);
            float v00 = lerp1(e0.x, e0.y, f2[p]);
            float v01 = lerp1(e1.x, e1.y, f2[p]);
            float v10 = lerp1(e2.x, e2.y, f2[p]);
            float v11 = lerp1(e3.x, e3.y, f2[p]);
            float v0  = lerp1(v00, v01, f1[p]);
            float v1  = lerp1(v10, v11, f1[p]);
            rp[p - 4] = lerp1(v0, v1, f0[p]);
        }
        __stcs(o + 1, res);
    }
}

extern "C" void kernel_launch(void* const* d_in, const int* in_sizes, int n_in,
                              void* d_out, int out_size)
{
    const float* y  = (const float*)d_in[0];   // (8, 64,64,64)
    const float* xn = (const float*)d_in[1];   // (8, 96^3, 3)
    float* out      = (float*)d_out;           // (8, 96^3)

    const int RTOTAL = 8 * 63 * 63 * 16;       // 508,032
    repack_kernel<<<(RTOTAL + 255) / 256, 256>>>(y);

    int total8 = out_size / 8;                 // 884,736 = 3456 * 256
    trilerp_kernel<<<total8 / 256, 256>>>(xn, out);
}